// round 6
// baseline (speedup 1.0000x reference)
#include <cuda_runtime.h>

// Problem constants (match reference module)
namespace {
constexpr int kB = 32, kT = 200, kR = 4096, kC = 81;
constexpr float kIouTh = 0.7f;
constexpr int kThreads = 64;                    // 2 warps/block
constexpr int kIlp = 2;                         // proposals per thread
constexpr int kRPerBlock = kThreads * kIlp;     // 128
constexpr int kBlocksPerB = kR / kRPerBlock;    // 32
constexpr int kNBlocks = kB * kBlocksPerB;      // 1024 -> 6.92/SM, max 7 (balanced)
}

// Per-block partials: [npos, ce_sum, acc_sum, sl1_sum]
__device__ float g_partials[kNBlocks][4];
__device__ unsigned int g_done = 0;             // reset to 0 by last block each launch

__device__ __forceinline__ float warp_sum(float v) {
#pragma unroll
    for (int o = 16; o > 0; o >>= 1) v += __shfl_down_sync(0xffffffffu, v, o);
    return v;
}

__global__ __launch_bounds__(kThreads) void rcnn_main(
    const float4* __restrict__ nms_reg,   // [B,R,4]
    const float4* __restrict__ rcnn_reg,  // [B,R,4]
    const float*  __restrict__ rcnn_cls,  // [B,R,C]
    const float4* __restrict__ bboxes,    // [B,T,4]
    const int*    __restrict__ classes,   // [B,T]
    float* __restrict__ out)              // [3]
{
    __shared__ float4 s_box[kT];
    __shared__ float  s_area[kT];
    __shared__ int    s_cls[kT];

    const int b = blockIdx.x / kBlocksPerB;
    const int chunk = blockIdx.x % kBlocksPerB;
    const int tid = threadIdx.x;

    for (int i = tid; i < kT; i += kThreads) {
        float4 bb = bboxes[b * kT + i];
        s_box[i] = bb;
        s_area[i] = (bb.z - bb.x) * (bb.w - bb.y);
        s_cls[i] = classes[b * kT + i];
    }
    __syncthreads();

    // Contiguous mapping: positives (r < T) cluster into the first chunks of
    // each batch -> the softmax epilogue runs SIMD-dense in a few warps.
    float4 a[kIlp];
    float areaA[kIlp], binter[kIlp], bden[kIlp];
    int bidx[kIlp], r[kIlp];
#pragma unroll
    for (int i = 0; i < kIlp; i++) {
        r[i] = chunk * kRPerBlock + i * kThreads + tid;
        a[i] = nms_reg[b * kR + r[i]];
        areaA[i] = (a[i].z - a[i].x) * (a[i].w - a[i].y);
        binter[i] = 0.f;   // all-zero IoUs -> argmax = 0 (first occurrence)
        bden[i]   = 1.f;
        bidx[i]   = 0;
    }

    // ---- IoU argmax over T GT boxes (division-free rational compare) ----
    // The 2 LDS per t are amortized over kIlp=2 proposals -> LDS demand stays
    // under the per-SMSP crossbar floor, so fp issue isn't MIO-throttled.
    // iw unclamped: negative iw -> inter <= 0 can never win (binter >= 0,
    // bden > 0, den > 0); any selected (inter, den) match reference fl ops.
#pragma unroll 4
    for (int t = 0; t < kT; ++t) {
        float4 bb = s_box[t];
        float  ab = s_area[t];
#pragma unroll
        for (int i = 0; i < kIlp; i++) {
            float tt = fmaxf(a[i].x, bb.x);
            float ll = fmaxf(a[i].y, bb.y);
            float bo = fminf(a[i].z, bb.z);
            float rr = fminf(a[i].w, bb.w);
            float ih = fmaxf(bo - tt, 0.f);
            float iw = rr - ll;
            float inter = ih * iw;
            float den = (areaA[i] + ab) - inter;   // left-assoc, matches ref
            // inter/den > binter/bden  <=>  inter*bden > binter*den
            bool upd = inter * bden[i] > binter[i] * den;
            binter[i] = upd ? inter : binter[i];
            bden[i]   = upd ? den   : bden[i];
            bidx[i]   = upd ? t     : bidx[i];
        }
    }

    // ---- per-thread loss contributions over positives ----
    float cnt = 0.f, ce_s = 0.f, acc_s = 0.f, sl1_s = 0.f;
#pragma unroll
    for (int i = 0; i < kIlp; i++) {
        float iou = binter[i] / bden[i];          // exact IEEE divide
        if (iou > kIouTh) {
            cnt += 1.f;

            // Cross-entropy + argmax accuracy over C=81 logits
            const float* p = rcnn_cls + (size_t)(b * kR + r[i]) * kC;
            float m = p[0];
            int am = 0;
            for (int c = 1; c < kC; ++c) {
                float v = p[c];
                if (v > m) { m = v; am = c; }     // strict > keeps first occ.
            }
            float s = 0.f;
            for (int c = 0; c < kC; ++c) s += expf(p[c] - m);
            int label = s_cls[bidx[i]];
            ce_s += -(p[label] - m - logf(s));
            acc_s += (am == label) ? 1.f : 0.f;

            // Smooth-L1 regression vs stride-rounded offsets
            float4 gb = s_box[bidx[i]];
            float r0 = rintf(gb.x * 0.0625f) * 16.f;  // jnp.round = RN-even
            float r1 = rintf(gb.y * 0.0625f) * 16.f;
            float r2 = rintf(gb.z * 0.0625f) * 16.f;
            float r3 = rintf(gb.w * 0.0625f) * 16.f;
            float h = r2 - r0; h = (h == 0.f) ? 1.f : h;
            float w = r3 - r1; w = (w == 0.f) ? 1.f : w;
            float4 pr = rcnn_reg[b * kR + r[i]];
            float t0 = (gb.x - r0) / h, t1 = (gb.y - r1) / w;
            float t2 = (gb.z - r2) / h, t3 = (gb.w - r3) / w;
            float d;
            d = fabsf(pr.x - t0); sl1_s += (d < 1.f) ? 0.5f * d * d : d - 0.5f;
            d = fabsf(pr.y - t1); sl1_s += (d < 1.f) ? 0.5f * d * d : d - 0.5f;
            d = fabsf(pr.z - t2); sl1_s += (d < 1.f) ? 0.5f * d * d : d - 0.5f;
            d = fabsf(pr.w - t3); sl1_s += (d < 1.f) ? 0.5f * d * d : d - 0.5f;
        }
    }

    // ---- deterministic block reduction (2 warps) ----
    __shared__ float s_red[kThreads / 32][4];
    cnt = warp_sum(cnt); ce_s = warp_sum(ce_s);
    acc_s = warp_sum(acc_s); sl1_s = warp_sum(sl1_s);
    int wid = tid >> 5, lid = tid & 31;
    if (lid == 0) {
        s_red[wid][0] = cnt; s_red[wid][1] = ce_s;
        s_red[wid][2] = acc_s; s_red[wid][3] = sl1_s;
    }
    __syncthreads();
    if (tid == 0) {
        float v0 = 0.f, v1 = 0.f, v2 = 0.f, v3 = 0.f;
#pragma unroll
        for (int k = 0; k < kThreads / 32; ++k) {
            v0 += s_red[k][0]; v1 += s_red[k][1];
            v2 += s_red[k][2]; v3 += s_red[k][3];
        }
        g_partials[blockIdx.x][0] = v0;
        g_partials[blockIdx.x][1] = v1;
        g_partials[blockIdx.x][2] = v2;
        g_partials[blockIdx.x][3] = v3;
    }

    // ---- fused finalize: last block to finish reduces all partials ----
    __shared__ bool s_last;
    if (tid == 0) {
        __threadfence();
        unsigned int prev = atomicAdd(&g_done, 1u);
        s_last = (prev == (unsigned)(kNBlocks - 1));
    }
    __syncthreads();
    if (!s_last) return;

    float v0 = 0.f, v1 = 0.f, v2 = 0.f, v3 = 0.f;
#pragma unroll
    for (int k = 0; k < kNBlocks / kThreads; ++k) {
        int idx = tid + k * kThreads;
        const volatile float* gp = &g_partials[idx][0];
        v0 += gp[0]; v1 += gp[1]; v2 += gp[2]; v3 += gp[3];
    }
    v0 = warp_sum(v0); v1 = warp_sum(v1); v2 = warp_sum(v2); v3 = warp_sum(v3);
    __shared__ float s_fin[kThreads / 32][4];
    if (lid == 0) {
        s_fin[wid][0] = v0; s_fin[wid][1] = v1;
        s_fin[wid][2] = v2; s_fin[wid][3] = v3;
    }
    __syncthreads();
    if (tid == 0) {
        float npos = 0.f, ce = 0.f, acc = 0.f, sl1 = 0.f;
        for (int k = 0; k < kThreads / 32; ++k) {
            npos += s_fin[k][0]; ce += s_fin[k][1];
            acc += s_fin[k][2]; sl1 += s_fin[k][3];
        }
        float denom = fmaxf(npos, 1.f);
        bool has = npos > 0.f;
        out[0] = has ? ce / denom : 0.f;   // cls_loss
        out[1] = has ? sl1 / denom : 0.f;  // reg_loss (sum of per-coord means)
        out[2] = has ? acc / denom : 0.f;  // accuracy
        g_done = 0;                         // reset for next graph replay
    }
}

extern "C" void kernel_launch(void* const* d_in, const int* in_sizes, int n_in,
                              void* d_out, int out_size) {
    // metadata order: nms_reg, nms_cls (unused), rcnn_reg, rcnn_cls, bboxes, classes
    const float4* nms_reg  = (const float4*)d_in[0];
    const float4* rcnn_reg = (const float4*)d_in[2];
    const float*  rcnn_cls = (const float*)d_in[3];
    const float4* bboxes   = (const float4*)d_in[4];
    const int*    classes  = (const int*)d_in[5];
    (void)in_sizes; (void)n_in; (void)out_size;

    rcnn_main<<<kNBlocks, kThreads>>>(nms_reg, rcnn_reg, rcnn_cls, bboxes, classes,
                                      (float*)d_out);
}

// round 7
// speedup vs baseline: 1.3258x; 1.3258x over previous
#include <cuda_runtime.h>

// Problem constants (match reference module)
namespace {
constexpr int kB = 32, kT = 200, kR = 4096, kC = 81;
constexpr float kIouTh = 0.7f;
constexpr int kThreads = 128;                   // 4 warps/block
constexpr int kBlocksPerB = kR / kThreads;      // 32 chunks per batch
constexpr int kNBlocks = kB * kBlocksPerB;      // 1024 -> 6.92/SM, max 7 (balanced)
constexpr int kTile = 8;                        // GT boxes prefetched per batch
}

// Per-block partials: (npos, ce_sum, acc_sum, sl1_sum) — float4 for 128-bit ld/st
__device__ float4 g_partials[kNBlocks];
__device__ unsigned int g_done = 0;             // reset to 0 by last block each launch

__device__ __forceinline__ float warp_sum(float v) {
#pragma unroll
    for (int o = 16; o > 0; o >>= 1) v += __shfl_down_sync(0xffffffffu, v, o);
    return v;
}

__device__ __forceinline__ float4 ldcv4(const float4* p) {
    float4 v;
    asm volatile("ld.global.cv.v4.f32 {%0,%1,%2,%3}, [%4];"
                 : "=f"(v.x), "=f"(v.y), "=f"(v.z), "=f"(v.w) : "l"(p));
    return v;
}

__global__ __launch_bounds__(kThreads, 7) void rcnn_main(
    const float4* __restrict__ nms_reg,   // [B,R,4]
    const float4* __restrict__ rcnn_reg,  // [B,R,4]
    const float*  __restrict__ rcnn_cls,  // [B,R,C]
    const float4* __restrict__ bboxes,    // [B,T,4]
    const int*    __restrict__ classes,   // [B,T]
    float* __restrict__ out)              // [3]
{
    __shared__ float4 s_box[kT];
    __shared__ float  s_area[kT];
    __shared__ int    s_cls[kT];

    const int b = blockIdx.x / kBlocksPerB;
    const int chunk = blockIdx.x % kBlocksPerB;
    const int tid = threadIdx.x;
    const int lid = tid & 31;
    const unsigned FULL = 0xffffffffu;

    for (int i = tid; i < kT; i += kThreads) {
        float4 bb = bboxes[b * kT + i];
        s_box[i] = bb;
        s_area[i] = (bb.z - bb.x) * (bb.w - bb.y);
        s_cls[i] = classes[b * kT + i];
    }
    __syncthreads();

    // Strided mapping: positives (r < T) land on lanes 0..6 of warp 0 of every
    // block -> the cooperative epilogue is spread evenly over all 1024 blocks.
    const int r = chunk + kBlocksPerB * tid;

    const float4 a = nms_reg[b * kR + r];
    const float areaA = (a.z - a.x) * (a.w - a.y);
    float binter = 0.f;   // all-zero IoUs -> argmax = 0 (first occurrence)
    float bden   = 1.f;
    int   bidx   = 0;

    // ---- IoU argmax over T GT boxes (division-free rational compare) ----
    // Tile-8: batch the 16 LDS up front (MLP), then 8 pure-arith iterations,
    // hiding the 29-cyc LDS latency. iw unclamped: negative iw -> inter <= 0
    // can never win (binter >= 0, bden > 0, den > 0); selected (inter, den)
    // match the reference's fl ops exactly.
#pragma unroll 1
    for (int t0 = 0; t0 < kT; t0 += kTile) {
        float4 bbv[kTile];
        float  abv[kTile];
#pragma unroll
        for (int k = 0; k < kTile; ++k) {
            bbv[k] = s_box[t0 + k];
            abv[k] = s_area[t0 + k];
        }
#pragma unroll
        for (int k = 0; k < kTile; ++k) {
            float tt = fmaxf(a.x, bbv[k].x);
            float ll = fmaxf(a.y, bbv[k].y);
            float bo = fminf(a.z, bbv[k].z);
            float rr = fminf(a.w, bbv[k].w);
            float ih = fmaxf(bo - tt, 0.f);
            float iw = rr - ll;
            float inter = ih * iw;
            float den = (areaA + abv[k]) - inter;   // left-assoc, matches ref
            // inter/den > binter/bden  <=>  inter*bden > binter*den
            bool upd = inter * bden > binter * den;
            binter = upd ? inter : binter;
            bden   = upd ? den   : bden;
            bidx   = upd ? (t0 + k) : bidx;
        }
    }

    // ---- positivity + per-lane regression loss ----
    float iou = binter / bden;               // exact IEEE divide, ref-compatible
    bool pos = iou > kIouTh;
    float cnt = pos ? 1.f : 0.f;
    float ce_s = 0.f, acc_s = 0.f, sl1_s = 0.f;

    if (pos) {
        // Smooth-L1 regression vs stride-rounded offsets (cheap, per-lane)
        float4 gb = s_box[bidx];
        float r0 = rintf(gb.x * 0.0625f) * 16.f;   // jnp.round = RN-even = rintf
        float r1 = rintf(gb.y * 0.0625f) * 16.f;
        float r2 = rintf(gb.z * 0.0625f) * 16.f;
        float r3 = rintf(gb.w * 0.0625f) * 16.f;
        float h = r2 - r0; h = (h == 0.f) ? 1.f : h;
        float w = r3 - r1; w = (w == 0.f) ? 1.f : w;
        float4 pr = rcnn_reg[b * kR + r];
        float t0 = (gb.x - r0) / h, t1 = (gb.y - r1) / w;
        float t2 = (gb.z - r2) / h, t3 = (gb.w - r3) / w;
        float d;
        d = fabsf(pr.x - t0); sl1_s += (d < 1.f) ? 0.5f * d * d : d - 0.5f;
        d = fabsf(pr.y - t1); sl1_s += (d < 1.f) ? 0.5f * d * d : d - 0.5f;
        d = fabsf(pr.z - t2); sl1_s += (d < 1.f) ? 0.5f * d * d : d - 0.5f;
        d = fabsf(pr.w - t3); sl1_s += (d < 1.f) ? 0.5f * d * d : d - 0.5f;
    }

    // ---- warp-cooperative CE + accuracy over C=81 logits ----
    // 32 lanes split the row (c = lid, lid+32, lid+64): coalesced loads, one
    // pass. Warp argmax keeps (max value, min index) = first occurrence,
    // identical to the reference's serial strict-> scan.
    unsigned act = __ballot_sync(FULL, pos);
    while (act) {
        int s = __ffs(act) - 1;
        act &= act - 1;
        int rs  = __shfl_sync(FULL, r, s);
        int bxs = __shfl_sync(FULL, bidx, s);
        const float* p = rcnn_cls + (size_t)(b * kR + rs) * kC;

        float v0 = p[lid];
        float v1 = p[lid + 32];
        float v2 = (lid < kC - 64) ? p[lid + 64] : 0.f;
        float m = v0; int am = lid;
        if (v1 > m) { m = v1; am = lid + 32; }
        if (lid < kC - 64 && v2 > m) { m = v2; am = lid + 64; }
#pragma unroll
        for (int o = 16; o > 0; o >>= 1) {
            float om = __shfl_down_sync(FULL, m, o);
            int   oa = __shfl_down_sync(FULL, am, o);
            if (om > m || (om == m && oa < am)) { m = om; am = oa; }
        }
        m  = __shfl_sync(FULL, m, 0);
        am = __shfl_sync(FULL, am, 0);

        float e = expf(v0 - m) + expf(v1 - m);
        if (lid < kC - 64) e += expf(v2 - m);
        e = warp_sum(e);
        e = __shfl_sync(FULL, e, 0);

        if (lid == s) {
            int label = s_cls[bxs];
            float pl = p[label];             // row is hot in L1/L2
            ce_s += -(pl - m - logf(e));
            acc_s += (am == label) ? 1.f : 0.f;
        }
    }

    // ---- deterministic block reduction (4 warps) ----
    __shared__ float s_red[kThreads / 32][4];
    cnt = warp_sum(cnt); ce_s = warp_sum(ce_s);
    acc_s = warp_sum(acc_s); sl1_s = warp_sum(sl1_s);
    int wid = tid >> 5;
    if (lid == 0) {
        s_red[wid][0] = cnt; s_red[wid][1] = ce_s;
        s_red[wid][2] = acc_s; s_red[wid][3] = sl1_s;
    }
    __syncthreads();
    if (tid == 0) {
        float v0 = 0.f, v1 = 0.f, v2 = 0.f, v3 = 0.f;
#pragma unroll
        for (int k = 0; k < kThreads / 32; ++k) {
            v0 += s_red[k][0]; v1 += s_red[k][1];
            v2 += s_red[k][2]; v3 += s_red[k][3];
        }
        g_partials[blockIdx.x] = make_float4(v0, v1, v2, v3);
    }

    // ---- fused finalize: last block to finish reduces all partials ----
    __shared__ bool s_last;
    if (tid == 0) {
        __threadfence();
        unsigned int prev = atomicAdd(&g_done, 1u);
        s_last = (prev == (unsigned)(kNBlocks - 1));
    }
    __syncthreads();
    if (!s_last) return;

    float v0 = 0.f, v1 = 0.f, v2 = 0.f, v3 = 0.f;
#pragma unroll
    for (int k = 0; k < kNBlocks / kThreads; ++k) {
        float4 gp = ldcv4(&g_partials[tid + k * kThreads]);  // L2-direct, vector
        v0 += gp.x; v1 += gp.y; v2 += gp.z; v3 += gp.w;
    }
    v0 = warp_sum(v0); v1 = warp_sum(v1); v2 = warp_sum(v2); v3 = warp_sum(v3);
    __shared__ float s_fin[kThreads / 32][4];
    if (lid == 0) {
        s_fin[wid][0] = v0; s_fin[wid][1] = v1;
        s_fin[wid][2] = v2; s_fin[wid][3] = v3;
    }
    __syncthreads();
    if (tid == 0) {
        float npos = 0.f, ce = 0.f, acc = 0.f, sl1 = 0.f;
        for (int k = 0; k < kThreads / 32; ++k) {
            npos += s_fin[k][0]; ce += s_fin[k][1];
            acc += s_fin[k][2]; sl1 += s_fin[k][3];
        }
        float denom = fmaxf(npos, 1.f);
        bool has = npos > 0.f;
        out[0] = has ? ce / denom : 0.f;   // cls_loss
        out[1] = has ? sl1 / denom : 0.f;  // reg_loss (sum of per-coord means)
        out[2] = has ? acc / denom : 0.f;  // accuracy
        g_done = 0;                         // reset for next graph replay
    }
}

extern "C" void kernel_launch(void* const* d_in, const int* in_sizes, int n_in,
                              void* d_out, int out_size) {
    // metadata order: nms_reg, nms_cls (unused), rcnn_reg, rcnn_cls, bboxes, classes
    const float4* nms_reg  = (const float4*)d_in[0];
    const float4* rcnn_reg = (const float4*)d_in[2];
    const float*  rcnn_cls = (const float*)d_in[3];
    const float4* bboxes   = (const float4*)d_in[4];
    const int*    classes  = (const int*)d_in[5];
    (void)in_sizes; (void)n_in; (void)out_size;

    rcnn_main<<<kNBlocks, kThreads>>>(nms_reg, rcnn_reg, rcnn_cls, bboxes, classes,
                                      (float*)d_out);
}